// round 16
// baseline (speedup 1.0000x reference)
#include <cuda_runtime.h>
#include <math.h>

#define N_IMG 16
#define A 360
#define R 360
#define H 256
#define W 256
#define RW 12                       // 360 bits -> 12 x 32-bit words per angle
#define APB 12                      // angles per block in peak kernel
#define NPB (A / APB)               // 30 peak blocks per image
#define DELTA_RHO_D (2.0 * 181.01933598375618 / 359.0)   // 2*sqrt(128^2+128^2)/359

__device__ float        g_blockmax[N_IMG * NPB];         // written every run, no init needed
__device__ unsigned int g_peak[N_IMG * A * RW];
__device__ float2       g_trig[A];                       // (cos, sin) per angle

// ---------------------------------------------------------------- peak bitmask (global-direct)
// grid (NPB, N_IMG), block 384 = 12 warps; warp w handles angle a0+w, all 360 r.
// (R9-measured-best version.)
__global__ void __launch_bounds__(384) dm_peak_kernel(const float* __restrict__ in) {
    __shared__ float s_red[12];

    const int n  = blockIdx.y;
    const int a0 = blockIdx.x * APB;
    const int warp = threadIdx.x >> 5;
    const int lane = threadIdx.x & 31;
    const float* img = in + (size_t)n * (A * R);

    // block (0,0) publishes the trig table (deterministic, written every call)
    if (blockIdx.x == 0 && n == 0 && threadIdx.x < A) {
        float th = (float)threadIdx.x * (float)(M_PI / 360.0);
        float s, c;
        __sincosf(th, &s, &c);
        g_trig[threadIdx.x] = make_float2(c, s);
    }

    const int a = a0 + warp;
    const float* rc = img + a * R;
    const float* rm = rc - R;                    // valid iff a > 0
    const float* rp = rc + R;                    // valid iff a < A-1
    const bool hm = (a > 0), hp = (a < A - 1);
    const float4 NEG4 = make_float4(-INFINITY, -INFINITY, -INFINITY, -INFINITY);

    float rowmax = 0.0f;                         // max of this warp's own row (values in (0,1))
    unsigned int* dst = &g_peak[((size_t)n * A + a) * RW];

    #pragma unroll
    for (int c = 0; c < 3; c++) {
        const int r0 = c * 128 + lane * 4;
        const bool act = (r0 < R);               // chunk 2: lanes 0..25 active
        float4 c4, vm4;
        if (act) {
            c4        = __ldg((const float4*)(rc + r0));   // rows are 16B-aligned (1440B)
            float4 m4 = hm ? __ldg((const float4*)(rm + r0)) : NEG4;
            float4 p4 = hp ? __ldg((const float4*)(rp + r0)) : NEG4;
            vm4.x = fmaxf(fmaxf(m4.x, p4.x), c4.x);
            vm4.y = fmaxf(fmaxf(m4.y, p4.y), c4.y);
            vm4.z = fmaxf(fmaxf(m4.z, p4.z), c4.z);
            vm4.w = fmaxf(fmaxf(m4.w, p4.w), c4.w);
            rowmax = fmaxf(rowmax, fmaxf(fmaxf(c4.x, c4.y), fmaxf(c4.z, c4.w)));
        } else {
            c4  = NEG4;
            vm4 = NEG4;
        }
        // vertical-max of left/right neighbors across lanes / chunk edges
        float vmL = __shfl_up_sync(0xFFFFFFFFu, vm4.w, 1);
        float vmR = __shfl_down_sync(0xFFFFFFFFu, vm4.x, 1);
        if (lane == 0) {
            int rr = r0 - 1;
            if (rr >= 0) {
                float t = rc[rr];
                if (hm) t = fmaxf(t, rm[rr]);
                if (hp) t = fmaxf(t, rp[rr]);
                vmL = t;
            } else {
                vmL = -INFINITY;
            }
        }
        if (c < 2 && lane == 31) {
            int rr = r0 + 4;                     // 128 or 256, always in range
            float t = rc[rr];
            if (hm) t = fmaxf(t, rm[rr]);
            if (hp) t = fmaxf(t, rp[rr]);
            vmR = t;
        }
        // pk = (v == 3x3-pooled max)  <=>  v >= hmax3(vmax3)
        unsigned int nib = 0;
        if (act) {
            if (c4.x >= fmaxf(vmL,   fmaxf(vm4.x, vm4.y))) nib |= 1u;
            if (c4.y >= fmaxf(vm4.x, fmaxf(vm4.y, vm4.z))) nib |= 2u;
            if (c4.z >= fmaxf(vm4.y, fmaxf(vm4.z, vm4.w))) nib |= 4u;
            if (c4.w >= fmaxf(vm4.z, fmaxf(vm4.w, vmR  ))) nib |= 8u;
        }
        // pack nibbles -> 4 words per chunk (lanes 8j..8j+7 form word j)
        unsigned int v = nib << ((lane & 7) * 4);
        v |= __shfl_xor_sync(0xFFFFFFFFu, v, 1);
        v |= __shfl_xor_sync(0xFFFFFFFFu, v, 2);
        v |= __shfl_xor_sync(0xFFFFFFFFu, v, 4);
        if ((lane & 7) == 0) dst[c * 4 + (lane >> 3)] = v;
    }

    // per-block (12-row) max -> g_blockmax; union over blocks covers the image
    #pragma unroll
    for (int o = 16; o; o >>= 1) rowmax = fmaxf(rowmax, __shfl_xor_sync(0xFFFFFFFFu, rowmax, o));
    if (lane == 0) s_red[warp] = rowmax;
    __syncthreads();
    if (threadIdx.x < 32) {
        float m = (threadIdx.x < 12) ? s_red[threadIdx.x] : 0.0f;
        #pragma unroll
        for (int o = 8; o; o >>= 1) m = fmaxf(m, __shfl_xor_sync(0xFFFFFFFFu, m, o));
        if (threadIdx.x == 0) g_blockmax[n * NPB + blockIdx.x] = m;
    }
}

// ---------------------------------------------------------------- threshold filter
// grid (NPB, N_IMG), block 160; clears peak bits whose hough value <= 0.5*gmax.
__global__ void __launch_bounds__(160) dm_filter_kernel(const float* __restrict__ in) {
    __shared__ float s_thr;
    const int n = blockIdx.y;
    if (threadIdx.x < 32) {
        float bm = (threadIdx.x < NPB) ? g_blockmax[n * NPB + threadIdx.x] : 0.0f;
        #pragma unroll
        for (int o = 16; o; o >>= 1) bm = fmaxf(bm, __shfl_xor_sync(0xFFFFFFFFu, bm, o));
        if (threadIdx.x == 0) s_thr = 0.5f * bm;
    }
    __syncthreads();
    const float thr = s_thr;

    const int wi = threadIdx.x;                  // word within this block's 12 angles
    if (wi < APB * RW) {
        const int a = blockIdx.x * APB + wi / RW;
        const int rbase = (wi % RW) * 32;
        const size_t widx = ((size_t)n * A + a) * RW + (wi % RW);
        unsigned int word = g_peak[widx];
        if (word) {
            const float* row = in + (size_t)n * (A * R) + a * R;
            unsigned int keep = word;
            unsigned int it = word;
            while (it) {
                int b = __ffs(it) - 1;
                it &= it - 1u;
                if (row[rbase + b] <= thr) keep &= ~(1u << b);
            }
            if (keep != word) g_peak[widx] = keep;
        }
    }
}

// ---------------------------------------------------------------- pixel mask (4 px/thread, 2D tiles,
// warp-uniform 96-bit candidate window read directly from L1-resident global).
// grid (64, N_IMG), block 256 = 8 warps; block covers a 32x32 tile; each warp a
// 32x4 sub-tile (lanes: 8 across x 4 rows). No smem, no barriers: the per-angle
// table reads are warp-uniform broadcast LDGs of a ~2.2 KB hot region.
__global__ void __launch_bounds__(256) dm_mask_kernel(float* __restrict__ out) {
    const int n = blockIdx.y;
    const unsigned int* __restrict__ pk_img = g_peak + (size_t)n * A * RW;

    const float delta     = (float)DELTA_RHO_D;
    const float inv_delta = 1.0f / (float)DELTA_RHO_D;
    float* oimg = out + (size_t)n * (H * W);

    const int warp = threadIdx.x >> 5;
    const int lane = threadIdx.x & 31;
    const int tile_x = (blockIdx.x & 7) << 5;         // 8 tiles across
    const int tile_y = (blockIdx.x >> 3) << 5;        // 8 tiles down
    const int w  = tile_x + ((lane & 7) << 2);        // 4 consecutive px in x
    const int h  = tile_y + (warp << 2) + (lane >> 3);
    const float x0 = (float)w - 127.5f;
    const float y  = (float)h - 127.5f;

    // warp-uniform tile-corner coordinates
    const float xl = (float)tile_x - 127.5f;
    const float xh = xl + 31.0f;
    const float yl = (float)(tile_y + (warp << 2)) - 127.5f;
    const float yh = yl + 3.0f;

    float res[4] = {0.0f, 0.0f, 0.0f, 0.0f};
    unsigned int act = 0xFu;

    for (int a = 0; a < A && act; a++) {
        float2 cs = __ldg(&g_trig[a]);                // warp-uniform broadcast
        const float c = cs.x, s = cs.y;               // s >= 0 for theta in [0, pi)

        // ---- warp-uniform candidate window, up to ~38 bins -> 96-bit (3 words) ----
        float rminw = fminf(c * xl, c * xh) + s * yl;
        float rmaxw = fmaxf(c * xl, c * xh) + s * yh;
        int lo = (int)(rminw * inv_delta + 180.0f) - 3;   // value in (0,360): trunc == floor
        int hi = (int)(rmaxw * inv_delta + 180.0f) + 3;
        if (lo < 0)     lo = 0;
        if (hi > R - 1) hi = R - 1;

        const int base = lo >> 5;                     // 0..11
        unsigned int wa = __ldg(pk_img + a * RW + base);
        unsigned int wb = (base + 1 < RW) ? __ldg(pk_img + a * RW + base + 1) : 0u;
        unsigned int wc = (base + 2 < RW) ? __ldg(pk_img + a * RW + base + 2) : 0u;
        unsigned long long low = (unsigned long long)wa | ((unsigned long long)wb << 32);

        // warp-uniform skip test over [lo, hi] within the 96-bit window
        int s0 = lo - (base << 5);                    // 0..31
        int s1 = hi - (base << 5);                    // <= ~69
        {
            int t1 = s1 < 63 ? s1 : 63;
            int len = t1 - s0 + 1;                    // 1..64
            unsigned long long mlow = (len >= 64) ? ~0ull
                                                  : (((1ull << len) - 1ull) << s0);
            bool any = (low & mlow) != 0ull;
            if (s1 >= 64)
                any = any || ((wc & ((1u << (s1 - 63)) - 1u)) != 0u);
            if (!any) continue;
        }

        // ---- per-thread candidate confirm (7-bin sub-window; rebase if needed) ----
        float rho0 = c * x0 + s * y;
        #pragma unroll
        for (int i = 0; i < 4; i++) {
            if (!((act >> i) & 1u)) continue;
            float rho = rho0 + (float)i * c;
            int fl = (int)(rho * inv_delta + 180.0f);
            int li = fl - 3, hv = fl + 3;             // subset of [lo, hi] pre-clamp
            if (li < 0)     li = 0;
            if (hv > R - 1) hv = R - 1;
            int si0 = li - (base << 5);               // 0..~69
            int rrb = (base << 5);
            unsigned long long seg = low;
            if (si0 >= 32) {                          // rebase to bits 32..95 of the window
                seg = (low >> 32) | ((unsigned long long)wc << 32);
                si0 -= 32;
                rrb += 32;
            }
            int si1 = si0 + (hv - li);                // <= ~43 < 64
            unsigned long long cand = seg & (((1ull << (si1 - si0 + 1)) - 1ull) << si0);
            while (cand) {
                int b = __ffsll((long long)cand) - 1;
                cand &= cand - 1ull;
                int rr = rrb + b;
                float rv = (float)(rr - 180) * delta;     // matches reference rho_vals
                if (fabsf(rho - rv) < 3.0f) { res[i] = 1.0f; act &= ~(1u << i); break; }
            }
        }
    }
    *(float4*)(oimg + h * W + w) = make_float4(res[0], res[1], res[2], res[3]);
}

// ---------------------------------------------------------------- launch
extern "C" void kernel_launch(void* const* d_in, const int* in_sizes, int n_in,
                              void* d_out, int out_size) {
    const float* in = (const float*)d_in[0];
    float* out = (float*)d_out;

    dm_peak_kernel<<<dim3(NPB, N_IMG), 384>>>(in);
    dm_filter_kernel<<<dim3(NPB, N_IMG), 160>>>(in);
    dm_mask_kernel<<<dim3(64, N_IMG), 256>>>(out);
}

// round 17
// speedup vs baseline: 1.0125x; 1.0125x over previous
#include <cuda_runtime.h>
#include <math.h>

#define N_IMG 16
#define A 360
#define R 360
#define H 256
#define W 256
#define RW 12                       // 360 bits -> 12 x 32-bit words per angle
#define APB 12                      // angles per block in peak kernel
#define NPB (A / APB)               // 30 peak blocks per image
#define DELTA_RHO_D (2.0 * 181.01933598375618 / 359.0)   // 2*sqrt(128^2+128^2)/359

__device__ float        g_blockmax[N_IMG * NPB];         // written every run, no init needed
__device__ unsigned int g_peak[N_IMG * A * RW];
__device__ float2       g_trig[A];                       // (cos, sin) per angle

// ---------------------------------------------------------------- peak bitmask (global-direct)
// grid (NPB, N_IMG), block 384 = 12 warps; warp w handles angle a0+w, all 360 r.
// (R9-measured-best version: separable 3x3 max, float4 __ldg rows, shuffle packing.)
__global__ void __launch_bounds__(384) dm_peak_kernel(const float* __restrict__ in) {
    __shared__ float s_red[12];

    const int n  = blockIdx.y;
    const int a0 = blockIdx.x * APB;
    const int warp = threadIdx.x >> 5;
    const int lane = threadIdx.x & 31;
    const float* img = in + (size_t)n * (A * R);

    // block (0,0) publishes the trig table (deterministic, written every call)
    if (blockIdx.x == 0 && n == 0 && threadIdx.x < A) {
        float th = (float)threadIdx.x * (float)(M_PI / 360.0);
        float s, c;
        __sincosf(th, &s, &c);
        g_trig[threadIdx.x] = make_float2(c, s);
    }

    const int a = a0 + warp;
    const float* rc = img + a * R;
    const float* rm = rc - R;                    // valid iff a > 0
    const float* rp = rc + R;                    // valid iff a < A-1
    const bool hm = (a > 0), hp = (a < A - 1);
    const float4 NEG4 = make_float4(-INFINITY, -INFINITY, -INFINITY, -INFINITY);

    float rowmax = 0.0f;                         // max of this warp's own row (values in (0,1))
    unsigned int* dst = &g_peak[((size_t)n * A + a) * RW];

    #pragma unroll
    for (int c = 0; c < 3; c++) {
        const int r0 = c * 128 + lane * 4;
        const bool act = (r0 < R);               // chunk 2: lanes 0..25 active
        float4 c4, vm4;
        if (act) {
            c4        = __ldg((const float4*)(rc + r0));   // rows are 16B-aligned (1440B)
            float4 m4 = hm ? __ldg((const float4*)(rm + r0)) : NEG4;
            float4 p4 = hp ? __ldg((const float4*)(rp + r0)) : NEG4;
            vm4.x = fmaxf(fmaxf(m4.x, p4.x), c4.x);
            vm4.y = fmaxf(fmaxf(m4.y, p4.y), c4.y);
            vm4.z = fmaxf(fmaxf(m4.z, p4.z), c4.z);
            vm4.w = fmaxf(fmaxf(m4.w, p4.w), c4.w);
            rowmax = fmaxf(rowmax, fmaxf(fmaxf(c4.x, c4.y), fmaxf(c4.z, c4.w)));
        } else {
            c4  = NEG4;
            vm4 = NEG4;
        }
        // vertical-max of left/right neighbors across lanes / chunk edges
        float vmL = __shfl_up_sync(0xFFFFFFFFu, vm4.w, 1);
        float vmR = __shfl_down_sync(0xFFFFFFFFu, vm4.x, 1);
        if (lane == 0) {
            int rr = r0 - 1;
            if (rr >= 0) {
                float t = rc[rr];
                if (hm) t = fmaxf(t, rm[rr]);
                if (hp) t = fmaxf(t, rp[rr]);
                vmL = t;
            } else {
                vmL = -INFINITY;
            }
        }
        if (c < 2 && lane == 31) {
            int rr = r0 + 4;                     // 128 or 256, always in range
            float t = rc[rr];
            if (hm) t = fmaxf(t, rm[rr]);
            if (hp) t = fmaxf(t, rp[rr]);
            vmR = t;
        }
        // pk = (v == 3x3-pooled max)  <=>  v >= hmax3(vmax3)
        unsigned int nib = 0;
        if (act) {
            if (c4.x >= fmaxf(vmL,   fmaxf(vm4.x, vm4.y))) nib |= 1u;
            if (c4.y >= fmaxf(vm4.x, fmaxf(vm4.y, vm4.z))) nib |= 2u;
            if (c4.z >= fmaxf(vm4.y, fmaxf(vm4.z, vm4.w))) nib |= 4u;
            if (c4.w >= fmaxf(vm4.z, fmaxf(vm4.w, vmR  ))) nib |= 8u;
        }
        // pack nibbles -> 4 words per chunk (lanes 8j..8j+7 form word j)
        unsigned int v = nib << ((lane & 7) * 4);
        v |= __shfl_xor_sync(0xFFFFFFFFu, v, 1);
        v |= __shfl_xor_sync(0xFFFFFFFFu, v, 2);
        v |= __shfl_xor_sync(0xFFFFFFFFu, v, 4);
        if ((lane & 7) == 0) dst[c * 4 + (lane >> 3)] = v;
    }

    // per-block (12-row) max -> g_blockmax; union over blocks covers the image
    #pragma unroll
    for (int o = 16; o; o >>= 1) rowmax = fmaxf(rowmax, __shfl_xor_sync(0xFFFFFFFFu, rowmax, o));
    if (lane == 0) s_red[warp] = rowmax;
    __syncthreads();
    if (threadIdx.x < 32) {
        float m = (threadIdx.x < 12) ? s_red[threadIdx.x] : 0.0f;
        #pragma unroll
        for (int o = 8; o; o >>= 1) m = fmaxf(m, __shfl_xor_sync(0xFFFFFFFFu, m, o));
        if (threadIdx.x == 0) g_blockmax[n * NPB + blockIdx.x] = m;
    }
}

// ---------------------------------------------------------------- threshold filter
// grid (NPB, N_IMG), block 160; clears peak bits whose hough value <= 0.5*gmax.
__global__ void __launch_bounds__(160) dm_filter_kernel(const float* __restrict__ in) {
    __shared__ float s_thr;
    const int n = blockIdx.y;
    if (threadIdx.x < 32) {
        float bm = (threadIdx.x < NPB) ? g_blockmax[n * NPB + threadIdx.x] : 0.0f;
        #pragma unroll
        for (int o = 16; o; o >>= 1) bm = fmaxf(bm, __shfl_xor_sync(0xFFFFFFFFu, bm, o));
        if (threadIdx.x == 0) s_thr = 0.5f * bm;
    }
    __syncthreads();
    const float thr = s_thr;

    const int wi = threadIdx.x;                  // word within this block's 12 angles
    if (wi < APB * RW) {
        const int a = blockIdx.x * APB + wi / RW;
        const int rbase = (wi % RW) * 32;
        const size_t widx = ((size_t)n * A + a) * RW + (wi % RW);
        unsigned int word = g_peak[widx];
        if (word) {
            const float* row = in + (size_t)n * (A * R) + a * R;
            unsigned int keep = word;
            unsigned int it = word;
            while (it) {
                int b = __ffs(it) - 1;
                it &= it - 1u;
                if (row[rbase + b] <= thr) keep &= ~(1u << b);
            }
            if (keep != word) g_peak[widx] = keep;
        }
    }
}

// ---------------------------------------------------------------- pixel mask (4 px/thread, 2D tiles)
// grid (64, N_IMG), block 256 = 8 warps. Block covers a 32x32 pixel tile; each
// warp covers a 32x4 sub-tile (lanes: 8 across x 4 rows), so a warp's rho
// values span <= ~44 bins -> correlated hits -> early warp-coherent exit.
// (R9-measured-best structure; trig read via warp-uniform __ldg instead of smem.)
__global__ void __launch_bounds__(256) dm_mask_kernel(float* __restrict__ out) {
    __shared__ unsigned int s_peak[A * RW];   // 17.28 KB

    const int n = blockIdx.y;
    {
        const uint4* src = (const uint4*)&g_peak[(size_t)n * A * RW];
        uint4* dst = (uint4*)s_peak;
        for (int i = threadIdx.x; i < (A * RW) / 4; i += blockDim.x) dst[i] = src[i];
    }
    __syncthreads();

    const float delta     = (float)DELTA_RHO_D;
    const float inv_delta = 1.0f / (float)DELTA_RHO_D;
    float* oimg = out + (size_t)n * (H * W);

    const int warp = threadIdx.x >> 5;
    const int lane = threadIdx.x & 31;
    const int tile_x = (blockIdx.x & 7) << 5;         // 8 tiles across
    const int tile_y = (blockIdx.x >> 3) << 5;        // 8 tiles down
    const int w  = tile_x + ((lane & 7) << 2);        // 4 consecutive px in x
    const int h  = tile_y + (warp << 2) + (lane >> 3);
    const float x0 = (float)w - 127.5f;
    const float y  = (float)h - 127.5f;

    float res[4] = {0.0f, 0.0f, 0.0f, 0.0f};
    unsigned int act = 0xFu;

    for (int a = 0; a < A && act; a++) {
        float2 cs = __ldg(&g_trig[a]);                // warp-uniform broadcast (L1-hot 2.9 KB)
        float rho0 = cs.x * x0 + cs.y * y;
        float rho3 = rho0 + 3.0f * cs.x;
        float rmin = fminf(rho0, rho3);
        float rmax = fmaxf(rho0, rho3);
        // combined window over the 4 pixels: span <= 7 + 3 bins < 64
        int lo = (int)(rmin * inv_delta + 180.0f) - 3;   // rc in (0,360): trunc == floor
        int hi = (int)(rmax * inv_delta + 180.0f) + 3;
        if (lo < 0)     lo = 0;
        if (hi > R - 1) hi = R - 1;

        const unsigned int* pw = &s_peak[a * RW];
        int w0 = lo >> 5;
        int w1 = hi >> 5;
        unsigned long long pk64 = (unsigned long long)pw[w0];
        if (w1 != w0) pk64 |= ((unsigned long long)pw[w1]) << 32;
        int s0 = lo - (w0 << 5);
        int s1 = hi - (w0 << 5);                 // < 64
        pk64 &= (((1ull << (s1 - s0 + 1)) - 1ull) << s0);
        if (!pk64) continue;                     // fast path: no candidate for any of the 4

        #pragma unroll
        for (int i = 0; i < 4; i++) {
            if (!((act >> i) & 1u)) continue;
            float rho = rho0 + (float)i * cs.x;
            int fl = (int)(rho * inv_delta + 180.0f);
            int li = fl - 3, hv = fl + 3;
            if (li < 0)     li = 0;
            if (hv > R - 1) hv = R - 1;
            int si0 = li - (w0 << 5);            // >= s0 >= 0
            int si1 = hv - (w0 << 5);            // <= s1 < 64
            unsigned long long cand = pk64 & (((1ull << (si1 - si0 + 1)) - 1ull) << si0);
            while (cand) {
                int b = __ffsll((long long)cand) - 1;
                cand &= cand - 1ull;
                int rr = (w0 << 5) + b;
                float rv = (float)(rr - 180) * delta;     // matches reference rho_vals
                if (fabsf(rho - rv) < 3.0f) { res[i] = 1.0f; act &= ~(1u << i); break; }
            }
        }
    }
    *(float4*)(oimg + h * W + w) = make_float4(res[0], res[1], res[2], res[3]);
}

// ---------------------------------------------------------------- launch
extern "C" void kernel_launch(void* const* d_in, const int* in_sizes, int n_in,
                              void* d_out, int out_size) {
    const float* in = (const float*)d_in[0];
    float* out = (float*)d_out;

    dm_peak_kernel<<<dim3(NPB, N_IMG), 384>>>(in);
    dm_filter_kernel<<<dim3(NPB, N_IMG), 160>>>(in);
    dm_mask_kernel<<<dim3(64, N_IMG), 256>>>(out);
}